// round 14
// baseline (speedup 1.0000x reference)
#include <cuda_runtime.h>
#include <cuda_bf16.h>
#include <mma.h>
#include <math_constants.h>

using namespace nvcuda;

#define NB 64
#define NM 1024
#define NN (NB*NM)      // 65536 nodes
#define NH 64
#define NK 16
#define HPAD 20         // padded k-stride for transposed hidden tile (msg)
#define CH 32           // knn candidate chunk
#define DLD 36          // dist tile leading dim (144 B, 16B-multiple for wmma store)
#define NCHUNK (NM/CH)  // 32

// ---------------- device scratch (static globals; no allocation) -------------
__device__ float g_h0[NN*NH];
__device__ float g_h1[NN*NH];
__device__ float g_a [NN*NH];
__device__ float g_e [NN*NH];
__device__ float g_sq[NN];
__device__ int   g_idx[NN*NK];
__device__ __nv_bfloat16 g_bhi[NN*NH];   // hi bf16 of current h
__device__ __nv_bfloat16 g_blo[NN*NH];   // lo residual bf16 of current h

// ---------------- helpers ----------------------------------------------------
__device__ __forceinline__ void cvt_hilo(float v, __nv_bfloat16& h, __nv_bfloat16& l) {
    h = __float2bfloat16(v);
    l = __float2bfloat16(v - __bfloat162float(h));
}
__device__ __forceinline__ unsigned pack_bf2(__nv_bfloat16 a, __nv_bfloat16 b) {
    return (unsigned)__bfloat16_as_ushort(a) | ((unsigned)__bfloat16_as_ushort(b) << 16);
}
__device__ __forceinline__ void cpa16(void* dst, const void* src) {
    unsigned d = (unsigned)__cvta_generic_to_shared(dst);
    asm volatile("cp.async.cg.shared.global [%0], [%1], 16;" :: "r"(d), "l"(src));
}

// ---------------- encoder: x[4] -> 32 -> 64 (ReLU both), + sqnorm + bf16 -----
__global__ void __launch_bounds__(256) enc_kernel(
    const float* __restrict__ x,
    const float* __restrict__ w1, const float* __restrict__ b1,
    const float* __restrict__ w2, const float* __restrict__ b2)
{
    __shared__ float w1s[4*32];
    __shared__ float b1s[32];
    __shared__ float w2s[32*64];
    __shared__ float b2s[64];
    int tid = threadIdx.x;
    if (tid < 128) w1s[tid] = w1[tid];
    if (tid < 32)  b1s[tid] = b1[tid];
    for (int q = tid; q < 32*64; q += 256) w2s[q] = w2[q];
    if (tid < 64)  b2s[tid] = b2[tid];
    __syncthreads();

    int n = blockIdx.x * 256 + tid;
    float4 xv = reinterpret_cast<const float4*>(x)[n];

    float hid[32];
#pragma unroll
    for (int o = 0; o < 32; o++) {
        float acc = b1s[o];
        acc += xv.x * w1s[o];
        acc += xv.y * w1s[32 + o];
        acc += xv.z * w1s[64 + o];
        acc += xv.w * w1s[96 + o];
        hid[o] = fmaxf(acc, 0.f);
    }

    float sq = 0.f;
    float4* outp = reinterpret_cast<float4*>(&g_h0[(size_t)n * NH]);
    uint2* bhp = reinterpret_cast<uint2*>(g_bhi + (size_t)n * NH);
    uint2* blp = reinterpret_cast<uint2*>(g_blo + (size_t)n * NH);
    const float4* w2v = reinterpret_cast<const float4*>(w2s);
    const float4* b2v = reinterpret_cast<const float4*>(b2s);
#pragma unroll
    for (int og = 0; og < 16; og++) {
        float4 acc = b2v[og];
#pragma unroll
        for (int j = 0; j < 32; j++) {
            float hv = hid[j];
            float4 wv = w2v[j*16 + og];
            acc.x += hv * wv.x; acc.y += hv * wv.y;
            acc.z += hv * wv.z; acc.w += hv * wv.w;
        }
        acc.x = fmaxf(acc.x, 0.f); acc.y = fmaxf(acc.y, 0.f);
        acc.z = fmaxf(acc.z, 0.f); acc.w = fmaxf(acc.w, 0.f);
        sq += acc.x*acc.x + acc.y*acc.y + acc.z*acc.z + acc.w*acc.w;
        outp[og] = acc;
        __nv_bfloat16 hx,lx,hy,ly,hz,lz,hw,lw;
        cvt_hilo(acc.x, hx, lx); cvt_hilo(acc.y, hy, ly);
        cvt_hilo(acc.z, hz, lz); cvt_hilo(acc.w, hw, lw);
        uint2 uh; uh.x = pack_bf2(hx, hy); uh.y = pack_bf2(hz, hw);
        uint2 ul; ul.x = pack_bf2(lx, ly); ul.y = pack_bf2(lz, lw);
        bhp[og] = uh; blp[og] = ul;
    }
    g_sq[n] = sq;
}

// ---------------- kNN v5: bf16 WMMA Gram, cp.async pipelined, 1 sync/chunk ---
__device__ __forceinline__ void knn_prefetch(
    __nv_bfloat16* Bh, __nv_bfloat16* Bl, float* sqs,
    int buf, int bbase, int jb, int tid)
{
#pragma unroll
    for (int u = 0; u < 4; u++) {
        int q = tid * 4 + u;                 // 0..511
        if (q < 256) {
            int row = q >> 3, off = (q & 7) * 8;
            cpa16(Bh + buf*CH*64 + row*64 + off,
                  g_bhi + (size_t)(bbase + jb + row)*64 + off);
        } else {
            int qq = q - 256;
            int row = qq >> 3, off = (qq & 7) * 8;
            cpa16(Bl + buf*CH*64 + row*64 + off,
                  g_blo + (size_t)(bbase + jb + row)*64 + off);
        }
    }
    if (tid < 8)
        cpa16(sqs + buf*CH + tid*4, g_sq + bbase + jb + tid*4);
}

__global__ void __launch_bounds__(128, 3) knn5_kernel()
{
    extern __shared__ char smraw[];
    float* Ds  = reinterpret_cast<float*>(smraw);                 // [128][DLD]
    float* sqs = Ds + 128*DLD;                                    // [2][CH]
    __nv_bfloat16* Ah = reinterpret_cast<__nv_bfloat16*>(sqs + 2*CH);  // [128][64]
    __nv_bfloat16* Al = Ah + 128*64;                              // [128][64]
    __nv_bfloat16* Bh = Al + 128*64;                              // [2][CH][64]
    __nv_bfloat16* Bl = Bh + 2*CH*64;                             // [2][CH][64]

    int tid  = threadIdx.x;
    int warp = tid >> 5;
    int b      = blockIdx.x >> 3;
    int istrip = (blockIdx.x & 7) * 128;
    int il     = istrip + tid;
    int bbase  = b * NM;

    // A tiles: copy own row of precomputed bf16 hi/lo (128 B each)
    {
        const float4* sh = reinterpret_cast<const float4*>(g_bhi + (size_t)(bbase + il)*64);
        const float4* sl = reinterpret_cast<const float4*>(g_blo + (size_t)(bbase + il)*64);
        float4* dh = reinterpret_cast<float4*>(Ah + tid*64);
        float4* dl = reinterpret_cast<float4*>(Al + tid*64);
#pragma unroll
        for (int u = 0; u < 8; u++) { dh[u] = sh[u]; dl[u] = sl[u]; }
    }
    knn_prefetch(Bh, Bl, sqs, 0, bbase, 0, tid);
    asm volatile("cp.async.commit_group;");

    float dist[NK]; int idx[NK];
#pragma unroll
    for (int k = 0; k < NK; k++) { dist[k] = CUDART_INF_F; idx[k] = 0; }
    float worst = CUDART_INF_F; int wpos = 0;
    int st = tid & (CH-1);

    for (int ci = 0; ci < NCHUNK; ci++) {
        int cur = ci & 1;
        int jb  = ci * CH;
        asm volatile("cp.async.wait_group 0;");
        __syncthreads();            // B[cur]/sqs[cur] visible; A ready (ci==0)

        wmma::fragment<wmma::accumulator, 16, 16, 16, float> acc[2][2];
#pragma unroll
        for (int mt = 0; mt < 2; mt++)
#pragma unroll
            for (int nt = 0; nt < 2; nt++) wmma::fill_fragment(acc[mt][nt], 0.f);

#pragma unroll
        for (int ks = 0; ks < 4; ks++) {
            wmma::fragment<wmma::matrix_a, 16, 16, 16, __nv_bfloat16, wmma::row_major> ahi[2], alo[2];
            wmma::fragment<wmma::matrix_b, 16, 16, 16, __nv_bfloat16, wmma::col_major> bhi[2], blo[2];
#pragma unroll
            for (int mt = 0; mt < 2; mt++) {
                int row0 = warp*32 + mt*16;
                wmma::load_matrix_sync(ahi[mt], Ah + row0*64 + ks*16, 64);
                wmma::load_matrix_sync(alo[mt], Al + row0*64 + ks*16, 64);
            }
#pragma unroll
            for (int nt = 0; nt < 2; nt++) {
                wmma::load_matrix_sync(bhi[nt], Bh + cur*CH*64 + nt*16*64 + ks*16, 64);
                wmma::load_matrix_sync(blo[nt], Bl + cur*CH*64 + nt*16*64 + ks*16, 64);
            }
#pragma unroll
            for (int mt = 0; mt < 2; mt++)
#pragma unroll
                for (int nt = 0; nt < 2; nt++) {
                    wmma::mma_sync(acc[mt][nt], ahi[mt], bhi[nt], acc[mt][nt]);
                    wmma::mma_sync(acc[mt][nt], ahi[mt], blo[nt], acc[mt][nt]);
                    wmma::mma_sync(acc[mt][nt], alo[mt], bhi[nt], acc[mt][nt]);
                }
        }

#pragma unroll
        for (int mt = 0; mt < 2; mt++)
#pragma unroll
            for (int nt = 0; nt < 2; nt++)
                wmma::store_matrix_sync(Ds + (warp*32 + mt*16)*DLD + nt*16,
                                        acc[mt][nt], DLD, wmma::mem_row_major);
        __syncwarp();               // Ds rows of this warp = rows scanned by its threads

        // staggered conflict-free scan of own row
#pragma unroll 4
        for (int jj0 = 0; jj0 < CH; jj0++) {
            int jj = (jj0 + st) & (CH-1);
            float d = sqs[cur*CH + jj] - 2.f * Ds[tid*DLD + jj];
            int j = jb + jj;
            if (d < worst && j != il) {
#pragma unroll
                for (int k = 0; k < NK; k++) if (k == wpos) { dist[k] = d; idx[k] = j; }
                worst = dist[0]; wpos = 0;
#pragma unroll
                for (int k = 1; k < NK; k++) if (dist[k] > worst) { worst = dist[k]; wpos = k; }
            }
        }

        if (ci + 1 < NCHUNK) {      // all warps are inside iter ci (top sync) -> !cur is free
            knn_prefetch(Bh, Bl, sqs, cur ^ 1, bbase, jb + CH, tid);
        }
        asm volatile("cp.async.commit_group;");   // uniform group count across threads
    }

    int i = bbase + il;
#pragma unroll
    for (int k = 0; k < NK; k++) g_idx[(size_t)i*NK + k] = bbase + idx[k];
}

// ---------------- prep: a = h@W1[:64] + b1,  e = h@W1[64:] -------------------
__global__ void __launch_bounds__(256) prep_kernel(
    const float* __restrict__ h,
    const float* __restrict__ w1, const float* __restrict__ b1)
{
    __shared__ float w1s[128*64];
    __shared__ float b1s[64];
    for (int q = threadIdx.x; q < 128*64; q += 256) w1s[q] = w1[q];
    if (threadIdx.x < 64) b1s[threadIdx.x] = b1[threadIdx.x];
    __syncthreads();

    int n = blockIdx.x * 256 + threadIdx.x;
    float hv[NH];
    {
        const float4* src = reinterpret_cast<const float4*>(h + (size_t)n * NH);
#pragma unroll
        for (int f = 0; f < 16; f++) {
            float4 v = src[f];
            hv[f*4+0] = v.x; hv[f*4+1] = v.y; hv[f*4+2] = v.z; hv[f*4+3] = v.w;
        }
    }

    const float4* wA = reinterpret_cast<const float4*>(w1s);            // rows 0..63
    const float4* wB = reinterpret_cast<const float4*>(w1s + 64*64);    // rows 64..127
    const float4* b1v = reinterpret_cast<const float4*>(b1s);
    float4* ap = reinterpret_cast<float4*>(&g_a[(size_t)n * NH]);
    float4* ep = reinterpret_cast<float4*>(&g_e[(size_t)n * NH]);

#pragma unroll 2
    for (int og = 0; og < 16; og++) {
        float4 acc = b1v[og];
#pragma unroll 8
        for (int f = 0; f < 64; f++) {
            float x = hv[f];
            float4 wv = wA[f*16 + og];
            acc.x += x*wv.x; acc.y += x*wv.y; acc.z += x*wv.z; acc.w += x*wv.w;
        }
        ap[og] = acc;
    }
#pragma unroll 2
    for (int og = 0; og < 16; og++) {
        float4 acc = make_float4(0.f, 0.f, 0.f, 0.f);
#pragma unroll 8
        for (int f = 0; f < 64; f++) {
            float x = hv[f];
            float4 wv = wB[f*16 + og];
            acc.x += x*wv.x; acc.y += x*wv.y; acc.z += x*wv.z; acc.w += x*wv.w;
        }
        ep[og] = acc;
    }
}

// ---------------- msg: hidden = relu(a_i + e_j - e_i); out = max_k hidden@W2+b2
// block = 128 threads = 4 warps; warp handles one node. (R4 scalar + bf16 epi.)
__global__ void __launch_bounds__(128) msg_kernel(
    const float* __restrict__ w2, const float* __restrict__ b2,
    float* __restrict__ hout)
{
    __shared__ float w2s[64*64];
    __shared__ float hidden[4][64*HPAD];     // [warp][o*HPAD + k]
    for (int q = threadIdx.x; q < 64*64; q += 128) w2s[q] = w2[q];
    __syncthreads();

    int warp = threadIdx.x >> 5;
    int l    = threadIdx.x & 31;
    int i    = blockIdx.x * 4 + warp;

    float a0 = g_a[(size_t)i*NH + l],      a1 = g_a[(size_t)i*NH + 32 + l];
    float e0 = g_e[(size_t)i*NH + l],      e1 = g_e[(size_t)i*NH + 32 + l];
    int jreg = (l < NK) ? g_idx[(size_t)i*NK + l] : 0;

    float* hid = hidden[warp];
#pragma unroll
    for (int k = 0; k < NK; k++) {
        int j = __shfl_sync(0xffffffffu, jreg, k);
        float ej0 = g_e[(size_t)j*NH + l];
        float ej1 = g_e[(size_t)j*NH + 32 + l];
        hid[l*HPAD + k]        = fmaxf(a0 + ej0 - e0, 0.f);
        hid[(l+32)*HPAD + k]   = fmaxf(a1 + ej1 - e1, 0.f);
    }
    __syncwarp();

    float accL[NK], accH[NK];
#pragma unroll
    for (int k = 0; k < NK; k++) { accL[k] = 0.f; accH[k] = 0.f; }

#pragma unroll 2
    for (int o = 0; o < 64; o++) {
        float wl = w2s[o*64 + l];
        float wh = w2s[o*64 + 32 + l];
        const float4* hp = reinterpret_cast<const float4*>(hid + o*HPAD);
        float4 h0v = hp[0], h1v = hp[1], h2v = hp[2], h3v = hp[3];
        float hk[16] = { h0v.x,h0v.y,h0v.z,h0v.w, h1v.x,h1v.y,h1v.z,h1v.w,
                         h2v.x,h2v.y,h2v.z,h2v.w, h3v.x,h3v.y,h3v.z,h3v.w };
#pragma unroll
        for (int k = 0; k < NK; k++) {
            accL[k] += hk[k] * wl;
            accH[k] += hk[k] * wh;
        }
    }

    float m0 = accL[0], m1 = accH[0];
#pragma unroll
    for (int k = 1; k < NK; k++) { m0 = fmaxf(m0, accL[k]); m1 = fmaxf(m1, accH[k]); }
    m0 += b2[l];
    m1 += b2[32 + l];

    hout[(size_t)i*NH + l]      = m0;
    hout[(size_t)i*NH + 32 + l] = m1;

    // bf16 hi/lo for next kNN
    __nv_bfloat16 bh, bl;
    cvt_hilo(m0, bh, bl);
    g_bhi[(size_t)i*NH + l] = bh;      g_blo[(size_t)i*NH + l] = bl;
    cvt_hilo(m1, bh, bl);
    g_bhi[(size_t)i*NH + 32 + l] = bh; g_blo[(size_t)i*NH + 32 + l] = bl;

    float s = m0*m0 + m1*m1;
#pragma unroll
    for (int off = 16; off; off >>= 1) s += __shfl_xor_sync(0xffffffffu, s, off);
    if (l == 0) g_sq[i] = s;
}

// ---------------- pool + output MLP -----------------------------------------
__global__ void __launch_bounds__(256) pool_kernel(
    const float* __restrict__ h,
    const float* __restrict__ w1, const float* __restrict__ b1,
    const float* __restrict__ w2, const float* __restrict__ b2,
    float* __restrict__ out)
{
    __shared__ float part[256];
    __shared__ float g[64];
    int b = blockIdx.x, tid = threadIdx.x;
    int c = tid & 63, rb = tid >> 6;
    float s = 0.f;
    for (int r = rb; r < NM; r += 4) s += h[(size_t)(b*NM + r)*NH + c];
    part[tid] = s;
    __syncthreads();
    if (tid < 64) g[tid] = (part[tid] + part[tid+64] + part[tid+128] + part[tid+192]) * (1.f/NM);
    __syncthreads();
    if (tid < 32) {
        float acc = b1[tid];
#pragma unroll 8
        for (int f = 0; f < 64; f++) acc += g[f] * w1[f*32 + tid];
        acc = fmaxf(acc, 0.f);
        acc *= w2[tid];
#pragma unroll
        for (int off = 16; off; off >>= 1) acc += __shfl_xor_sync(0xffffffffu, acc, off);
        if (tid == 0) out[b] = acc + b2[0];
    }
}

// ---------------- launch -----------------------------------------------------
extern "C" void kernel_launch(void* const* d_in, const int* in_sizes, int n_in,
                              void* d_out, int out_size)
{
    const float* x      = (const float*)d_in[0];
    const float* enc_w1 = (const float*)d_in[2];
    const float* enc_b1 = (const float*)d_in[3];
    const float* enc_w2 = (const float*)d_in[4];
    const float* enc_b2 = (const float*)d_in[5];
    const float* ec1_w1 = (const float*)d_in[6];
    const float* ec1_b1 = (const float*)d_in[7];
    const float* ec1_w2 = (const float*)d_in[8];
    const float* ec1_b2 = (const float*)d_in[9];
    const float* ec2_w1 = (const float*)d_in[10];
    const float* ec2_b1 = (const float*)d_in[11];
    const float* ec2_w2 = (const float*)d_in[12];
    const float* ec2_b2 = (const float*)d_in[13];
    const float* out_w1 = (const float*)d_in[14];
    const float* out_b1 = (const float*)d_in[15];
    const float* out_w2 = (const float*)d_in[16];
    const float* out_b2 = (const float*)d_in[17];
    float* out = (float*)d_out;

    float *h0, *h1;
    cudaGetSymbolAddress((void**)&h0, g_h0);
    cudaGetSymbolAddress((void**)&h1, g_h1);

    // Ds + sqs (float) + Ah/Al (bf16) + double-buffered Bh/Bl (bf16)
    const int KNN_SMEM = 128*DLD*4 + 2*CH*4 + 128*64*2*2 + 2*CH*64*2*2;  // 67840 B
    cudaFuncSetAttribute(knn5_kernel, cudaFuncAttributeMaxDynamicSharedMemorySize, KNN_SMEM);

    // encoder -> h0 (+ sqnorms + bf16 hi/lo)
    enc_kernel<<<NN/256, 256>>>(x, enc_w1, enc_b1, enc_w2, enc_b2);
    // EdgeConv 1
    knn5_kernel<<<NB*8, 128, KNN_SMEM>>>();
    prep_kernel<<<NN/256, 256>>>(h0, ec1_w1, ec1_b1);
    msg_kernel<<<NN/4, 128>>>(ec1_w2, ec1_b2, h1);
    // EdgeConv 2
    knn5_kernel<<<NB*8, 128, KNN_SMEM>>>();
    prep_kernel<<<NN/256, 256>>>(h1, ec2_w1, ec2_b1);
    msg_kernel<<<NN/4, 128>>>(ec2_w2, ec2_b2, h0);   // reuse h0 as h2
    // pool + output MLP
    pool_kernel<<<NB, 256>>>(h0, out_w1, out_b1, out_w2, out_b2, out);
}

// round 17
// speedup vs baseline: 1.2157x; 1.2157x over previous
#include <cuda_runtime.h>
#include <cuda_bf16.h>
#include <math_constants.h>
#include <cstdint>

#define NB 64
#define NM 1024
#define NN (NB*NM)      // 65536 nodes
#define NH 64
#define NK 16
#define HPAD 20         // padded k-stride for transposed hidden tile (msg)
#define CH 32           // knn candidate chunk
#define NCHUNK (NM/CH)  // 32
#define AST 36          // A/B smem row stride in u32 words (= 72 bf16 = 144 B)
#define DST 33          // D smem row stride in f32 words

// ---------------- device scratch (static globals; no allocation) -------------
__device__ float g_h0[NN*NH];
__device__ float g_h1[NN*NH];
__device__ float g_a [NN*NH];
__device__ float g_e [NN*NH];
__device__ float g_sq[NN];
__device__ int   g_idx[NN*NK];
__device__ __nv_bfloat16 g_bhi[NN*NH];   // hi bf16 of current h
__device__ __nv_bfloat16 g_blo[NN*NH];   // lo residual bf16 of current h

// ---------------- helpers ----------------------------------------------------
__device__ __forceinline__ void cvt_hilo(float v, __nv_bfloat16& h, __nv_bfloat16& l) {
    h = __float2bfloat16(v);
    l = __float2bfloat16(v - __bfloat162float(h));
}
__device__ __forceinline__ unsigned pack_bf2(__nv_bfloat16 a, __nv_bfloat16 b) {
    return (unsigned)__bfloat16_as_ushort(a) | ((unsigned)__bfloat16_as_ushort(b) << 16);
}
// mma.sync m16n8k16 bf16 (compute_103-legal HMMA), D/C fp32 in-place accumulate
__device__ __forceinline__ void mma16816(float* d,
    uint32_t a0, uint32_t a1, uint32_t a2, uint32_t a3,
    uint32_t b0, uint32_t b1)
{
    asm volatile(
        "mma.sync.aligned.m16n8k16.row.col.f32.bf16.bf16.f32 "
        "{%0,%1,%2,%3}, {%4,%5,%6,%7}, {%8,%9}, {%0,%1,%2,%3};"
        : "+f"(d[0]), "+f"(d[1]), "+f"(d[2]), "+f"(d[3])
        : "r"(a0), "r"(a1), "r"(a2), "r"(a3), "r"(b0), "r"(b1));
}

// ---------------- dummy kernel (profiling slot alignment) --------------------
__global__ void noop_kernel() {}

// ---------------- encoder: x[4] -> 32 -> 64 (ReLU both), + sqnorm + bf16 -----
__global__ void __launch_bounds__(256) enc_kernel(
    const float* __restrict__ x,
    const float* __restrict__ w1, const float* __restrict__ b1,
    const float* __restrict__ w2, const float* __restrict__ b2)
{
    __shared__ float w1s[4*32];
    __shared__ float b1s[32];
    __shared__ float w2s[32*64];
    __shared__ float b2s[64];
    int tid = threadIdx.x;
    if (tid < 128) w1s[tid] = w1[tid];
    if (tid < 32)  b1s[tid] = b1[tid];
    for (int q = tid; q < 32*64; q += 256) w2s[q] = w2[q];
    if (tid < 64)  b2s[tid] = b2[tid];
    __syncthreads();

    int n = blockIdx.x * 256 + tid;
    float4 xv = reinterpret_cast<const float4*>(x)[n];

    float hid[32];
#pragma unroll
    for (int o = 0; o < 32; o++) {
        float acc = b1s[o];
        acc += xv.x * w1s[o];
        acc += xv.y * w1s[32 + o];
        acc += xv.z * w1s[64 + o];
        acc += xv.w * w1s[96 + o];
        hid[o] = fmaxf(acc, 0.f);
    }

    float sq = 0.f;
    float4* outp = reinterpret_cast<float4*>(&g_h0[(size_t)n * NH]);
    uint2* bhp = reinterpret_cast<uint2*>(g_bhi + (size_t)n * NH);
    uint2* blp = reinterpret_cast<uint2*>(g_blo + (size_t)n * NH);
    const float4* w2v = reinterpret_cast<const float4*>(w2s);
    const float4* b2v = reinterpret_cast<const float4*>(b2s);
#pragma unroll
    for (int og = 0; og < 16; og++) {
        float4 acc = b2v[og];
#pragma unroll
        for (int j = 0; j < 32; j++) {
            float hv = hid[j];
            float4 wv = w2v[j*16 + og];
            acc.x += hv * wv.x; acc.y += hv * wv.y;
            acc.z += hv * wv.z; acc.w += hv * wv.w;
        }
        acc.x = fmaxf(acc.x, 0.f); acc.y = fmaxf(acc.y, 0.f);
        acc.z = fmaxf(acc.z, 0.f); acc.w = fmaxf(acc.w, 0.f);
        sq += acc.x*acc.x + acc.y*acc.y + acc.z*acc.z + acc.w*acc.w;
        outp[og] = acc;
        __nv_bfloat16 hx,lx,hy,ly,hz,lz,hw,lw;
        cvt_hilo(acc.x, hx, lx); cvt_hilo(acc.y, hy, ly);
        cvt_hilo(acc.z, hz, lz); cvt_hilo(acc.w, hw, lw);
        uint2 uh; uh.x = pack_bf2(hx, hy); uh.y = pack_bf2(hz, hw);
        uint2 ul; ul.x = pack_bf2(lx, ly); ul.y = pack_bf2(lz, lw);
        bhp[og] = uh; blp[og] = ul;
    }
    g_sq[n] = sq;
}

// ---------------- kNN v7: hand-rolled mma.sync bf16 Gram + fused top-16 ------
// block = 128 threads / 4 warps; warp owns 32 rows x 32 candidates per chunk.
// dot = hi.hi + hi.lo + lo.hi via 3-pass bf16 split (same numerics as R12 pass).
// Fragments loaded with plain LDS.32 per the canonical m16n8k16 layout
// (row stride 72 bf16 = 36 words -> bank-bijective across the warp).
// D accumulated in registers (12 mma per (mt,nt)); stored to Ds (stride 33,
// conflict-free scan), then threshold-replace top-16.
// SMEM (f32/u32 words): sqs[32] | Ds[4][32*33] | AhW[128*36] | AlW | BhW[32*36] | BlW
#define KNN_SMEM_BYTES ((32 + 4*32*DST + 2*128*AST + 2*CH*AST) * 4)   // 63104

__global__ void __launch_bounds__(128) knn7_kernel()
{
    extern __shared__ float sm[];
    float*    sqs = sm;                       // 32
    float*    Ds  = sm + 32;                  // 4*1056
    uint32_t* AhW = reinterpret_cast<uint32_t*>(Ds + 4*32*DST);   // 128*36
    uint32_t* AlW = AhW + 128*AST;
    uint32_t* BhW = AlW + 128*AST;            // 32*36
    uint32_t* BlW = BhW + CH*AST;

    int tid  = threadIdx.x;
    int warp = tid >> 5;
    int lane = tid & 31;
    int lq   = lane >> 2;        // 0..7
    int lr   = lane & 3;         // 0..3
    int b      = blockIdx.x >> 3;
    int istrip = (blockIdx.x & 7) * 128;
    int il     = istrip + tid;
    int bbase  = b * NM;

    // A tiles: thread copies its own row of precomputed bf16 hi/lo (8x uint4)
    {
        const uint4* sh = reinterpret_cast<const uint4*>(g_bhi + (size_t)(bbase + il)*64);
        const uint4* sl = reinterpret_cast<const uint4*>(g_blo + (size_t)(bbase + il)*64);
        uint4* dh = reinterpret_cast<uint4*>(AhW + tid*AST);
        uint4* dl = reinterpret_cast<uint4*>(AlW + tid*AST);
#pragma unroll
        for (int u = 0; u < 8; u++) { dh[u] = sh[u]; dl[u] = sl[u]; }
    }
    __syncthreads();

    float dist[NK]; int idx[NK];
#pragma unroll
    for (int k = 0; k < NK; k++) { dist[k] = CUDART_INF_F; idx[k] = 0; }
    float worst = CUDART_INF_F; int wpos = 0;

    float* Dw = Ds + warp * (32*DST);

    for (int ci = 0; ci < NCHUNK; ci++) {
        int jb = ci * CH;
        __syncthreads();          // prev scan done (sqs/Ds reads) before refill

        // B chunk: 4 threads per candidate row, 8 words each (2x uint4)
        {
            int r = tid >> 2, q = tid & 3;
            const uint4* ph = reinterpret_cast<const uint4*>(g_bhi + (size_t)(bbase + jb + r)*64) + q*2;
            const uint4* pl = reinterpret_cast<const uint4*>(g_blo + (size_t)(bbase + jb + r)*64) + q*2;
            uint4* dh = reinterpret_cast<uint4*>(BhW + r*AST + q*8);
            uint4* dl = reinterpret_cast<uint4*>(BlW + r*AST + q*8);
            dh[0] = ph[0]; dh[1] = ph[1];
            dl[0] = pl[0]; dl[1] = pl[1];
            if (tid < CH) sqs[tid] = g_sq[bbase + jb + tid];
        }
        __syncthreads();

        float d[2][4][4];
#pragma unroll
        for (int mt = 0; mt < 2; mt++)
#pragma unroll
            for (int nt = 0; nt < 4; nt++)
#pragma unroll
                for (int u = 0; u < 4; u++) d[mt][nt][u] = 0.f;

#pragma unroll
        for (int ks = 0; ks < 4; ks++) {
            // A fragments for both 16-row sub-tiles, hi and lo
            uint32_t ah[2][4], al[2][4];
#pragma unroll
            for (int mt = 0; mt < 2; mt++) {
                int r0 = warp*32 + mt*16 + lq;
                int base0 = r0*AST + ks*8 + lr;
                int base1 = (r0+8)*AST + ks*8 + lr;
                ah[mt][0] = AhW[base0];     ah[mt][1] = AhW[base1];
                ah[mt][2] = AhW[base0 + 4]; ah[mt][3] = AhW[base1 + 4];
                al[mt][0] = AlW[base0];     al[mt][1] = AlW[base1];
                al[mt][2] = AlW[base0 + 4]; al[mt][3] = AlW[base1 + 4];
            }
#pragma unroll
            for (int nt = 0; nt < 4; nt++) {
                int nb = (nt*8 + lq)*AST + ks*8 + lr;
                uint32_t bh0 = BhW[nb], bh1 = BhW[nb + 4];
                uint32_t bl0 = BlW[nb], bl1 = BlW[nb + 4];
#pragma unroll
                for (int mt = 0; mt < 2; mt++) {
                    mma16816(d[mt][nt], ah[mt][0], ah[mt][1], ah[mt][2], ah[mt][3], bh0, bh1);
                    mma16816(d[mt][nt], ah[mt][0], ah[mt][1], ah[mt][2], ah[mt][3], bl0, bl1);
                    mma16816(d[mt][nt], al[mt][0], al[mt][1], al[mt][2], al[mt][3], bh0, bh1);
                }
            }
        }

        // store D to warp-private Ds tile (canonical C layout)
#pragma unroll
        for (int mt = 0; mt < 2; mt++)
#pragma unroll
            for (int nt = 0; nt < 4; nt++) {
                int row = mt*16 + lq;
                int col = nt*8 + lr*2;
                Dw[row*DST + col]     = d[mt][nt][0];
                Dw[row*DST + col + 1] = d[mt][nt][1];
                Dw[(row+8)*DST + col]     = d[mt][nt][2];
                Dw[(row+8)*DST + col + 1] = d[mt][nt][3];
            }
        __syncwarp();             // Ds rows of this warp scanned by its own threads

        // scan own row (stride 33 -> conflict-free across lanes)
#pragma unroll 4
        for (int jj = 0; jj < CH; jj++) {
            float dd = sqs[jj] - 2.f * Dw[lane*DST + jj];
            int j = jb + jj;
            if (dd < worst && j != il) {
#pragma unroll
                for (int k = 0; k < NK; k++) if (k == wpos) { dist[k] = dd; idx[k] = j; }
                worst = dist[0]; wpos = 0;
#pragma unroll
                for (int k = 1; k < NK; k++) if (dist[k] > worst) { worst = dist[k]; wpos = k; }
            }
        }
    }

    int i = bbase + il;
#pragma unroll
    for (int k = 0; k < NK; k++) g_idx[(size_t)i*NK + k] = bbase + idx[k];
}

// ---------------- prep: a = h@W1[:64] + b1,  e = h@W1[64:] -------------------
__global__ void __launch_bounds__(256) prep_kernel(
    const float* __restrict__ h,
    const float* __restrict__ w1, const float* __restrict__ b1)
{
    __shared__ float w1s[128*64];
    __shared__ float b1s[64];
    for (int q = threadIdx.x; q < 128*64; q += 256) w1s[q] = w1[q];
    if (threadIdx.x < 64) b1s[threadIdx.x] = b1[threadIdx.x];
    __syncthreads();

    int n = blockIdx.x * 256 + threadIdx.x;
    float hv[NH];
    {
        const float4* src = reinterpret_cast<const float4*>(h + (size_t)n * NH);
#pragma unroll
        for (int f = 0; f < 16; f++) {
            float4 v = src[f];
            hv[f*4+0] = v.x; hv[f*4+1] = v.y; hv[f*4+2] = v.z; hv[f*4+3] = v.w;
        }
    }

    const float4* wA = reinterpret_cast<const float4*>(w1s);            // rows 0..63
    const float4* wB = reinterpret_cast<const float4*>(w1s + 64*64);    // rows 64..127
    const float4* b1v = reinterpret_cast<const float4*>(b1s);
    float4* ap = reinterpret_cast<float4*>(&g_a[(size_t)n * NH]);
    float4* ep = reinterpret_cast<float4*>(&g_e[(size_t)n * NH]);

#pragma unroll 2
    for (int og = 0; og < 16; og++) {
        float4 acc = b1v[og];
#pragma unroll 8
        for (int f = 0; f < 64; f++) {
            float x = hv[f];
            float4 wv = wA[f*16 + og];
            acc.x += x*wv.x; acc.y += x*wv.y; acc.z += x*wv.z; acc.w += x*wv.w;
        }
        ap[og] = acc;
    }
#pragma unroll 2
    for (int og = 0; og < 16; og++) {
        float4 acc = make_float4(0.f, 0.f, 0.f, 0.f);
#pragma unroll 8
        for (int f = 0; f < 64; f++) {
            float x = hv[f];
            float4 wv = wB[f*16 + og];
            acc.x += x*wv.x; acc.y += x*wv.y; acc.z += x*wv.z; acc.w += x*wv.w;
        }
        ep[og] = acc;
    }
}

// ---------------- msg: hidden = relu(a_i + e_j - e_i); out = max_k hidden@W2+b2
__global__ void __launch_bounds__(128) msg_kernel(
    const float* __restrict__ w2, const float* __restrict__ b2,
    float* __restrict__ hout)
{
    __shared__ float w2s[64*64];
    __shared__ float hidden[4][64*HPAD];     // [warp][o*HPAD + k]
    for (int q = threadIdx.x; q < 64*64; q += 128) w2s[q] = w2[q];
    __syncthreads();

    int warp = threadIdx.x >> 5;
    int l    = threadIdx.x & 31;
    int i    = blockIdx.x * 4 + warp;

    float a0 = g_a[(size_t)i*NH + l],      a1 = g_a[(size_t)i*NH + 32 + l];
    float e0 = g_e[(size_t)i*NH + l],      e1 = g_e[(size_t)i*NH + 32 + l];
    int jreg = (l < NK) ? g_idx[(size_t)i*NK + l] : 0;

    float* hid = hidden[warp];
#pragma unroll
    for (int k = 0; k < NK; k++) {
        int j = __shfl_sync(0xffffffffu, jreg, k);
        float ej0 = g_e[(size_t)j*NH + l];
        float ej1 = g_e[(size_t)j*NH + 32 + l];
        hid[l*HPAD + k]        = fmaxf(a0 + ej0 - e0, 0.f);
        hid[(l+32)*HPAD + k]   = fmaxf(a1 + ej1 - e1, 0.f);
    }
    __syncwarp();

    float accL[NK], accH[NK];
#pragma unroll
    for (int k = 0; k < NK; k++) { accL[k] = 0.f; accH[k] = 0.f; }

#pragma unroll 2
    for (int o = 0; o < 64; o++) {
        float wl = w2s[o*64 + l];
        float wh = w2s[o*64 + 32 + l];
        const float4* hp = reinterpret_cast<const float4*>(hid + o*HPAD);
        float4 h0v = hp[0], h1v = hp[1], h2v = hp[2], h3v = hp[3];
        float hk[16] = { h0v.x,h0v.y,h0v.z,h0v.w, h1v.x,h1v.y,h1v.z,h1v.w,
                         h2v.x,h2v.y,h2v.z,h2v.w, h3v.x,h3v.y,h3v.z,h3v.w };
#pragma unroll
        for (int k = 0; k < NK; k++) {
            accL[k] += hk[k] * wl;
            accH[k] += hk[k] * wh;
        }
    }

    float m0 = accL[0], m1 = accH[0];
#pragma unroll
    for (int k = 1; k < NK; k++) { m0 = fmaxf(m0, accL[k]); m1 = fmaxf(m1, accH[k]); }
    m0 += b2[l];
    m1 += b2[32 + l];

    hout[(size_t)i*NH + l]      = m0;
    hout[(size_t)i*NH + 32 + l] = m1;

    // bf16 hi/lo for next kNN
    __nv_bfloat16 bh, bl;
    cvt_hilo(m0, bh, bl);
    g_bhi[(size_t)i*NH + l] = bh;      g_blo[(size_t)i*NH + l] = bl;
    cvt_hilo(m1, bh, bl);
    g_bhi[(size_t)i*NH + 32 + l] = bh; g_blo[(size_t)i*NH + 32 + l] = bl;

    float s = m0*m0 + m1*m1;
#pragma unroll
    for (int off = 16; off; off >>= 1) s += __shfl_xor_sync(0xffffffffu, s, off);
    if (l == 0) g_sq[i] = s;
}

// ---------------- pool + output MLP -----------------------------------------
__global__ void __launch_bounds__(256) pool_kernel(
    const float* __restrict__ h,
    const float* __restrict__ w1, const float* __restrict__ b1,
    const float* __restrict__ w2, const float* __restrict__ b2,
    float* __restrict__ out)
{
    __shared__ float part[256];
    __shared__ float g[64];
    int b = blockIdx.x, tid = threadIdx.x;
    int c = tid & 63, rb = tid >> 6;
    float s = 0.f;
    for (int r = rb; r < NM; r += 4) s += h[(size_t)(b*NM + r)*NH + c];
    part[tid] = s;
    __syncthreads();
    if (tid < 64) g[tid] = (part[tid] + part[tid+64] + part[tid+128] + part[tid+192]) * (1.f/NM);
    __syncthreads();
    if (tid < 32) {
        float acc = b1[tid];
#pragma unroll 8
        for (int f = 0; f < 64; f++) acc += g[f] * w1[f*32 + tid];
        acc = fmaxf(acc, 0.f);
        acc *= w2[tid];
#pragma unroll
        for (int off = 16; off; off >>= 1) acc += __shfl_xor_sync(0xffffffffu, acc, off);
        if (tid == 0) out[b] = acc + b2[0];
    }
}

// ---------------- launch -----------------------------------------------------
extern "C" void kernel_launch(void* const* d_in, const int* in_sizes, int n_in,
                              void* d_out, int out_size)
{
    const float* x      = (const float*)d_in[0];
    const float* enc_w1 = (const float*)d_in[2];
    const float* enc_b1 = (const float*)d_in[3];
    const float* enc_w2 = (const float*)d_in[4];
    const float* enc_b2 = (const float*)d_in[5];
    const float* ec1_w1 = (const float*)d_in[6];
    const float* ec1_b1 = (const float*)d_in[7];
    const float* ec1_w2 = (const float*)d_in[8];
    const float* ec1_b2 = (const float*)d_in[9];
    const float* ec2_w1 = (const float*)d_in[10];
    const float* ec2_b1 = (const float*)d_in[11];
    const float* ec2_w2 = (const float*)d_in[12];
    const float* ec2_b2 = (const float*)d_in[13];
    const float* out_w1 = (const float*)d_in[14];
    const float* out_b1 = (const float*)d_in[15];
    const float* out_w2 = (const float*)d_in[16];
    const float* out_b2 = (const float*)d_in[17];
    float* out = (float*)d_out;

    float *h0, *h1;
    cudaGetSymbolAddress((void**)&h0, g_h0);
    cudaGetSymbolAddress((void**)&h1, g_h1);

    cudaFuncSetAttribute(knn7_kernel, cudaFuncAttributeMaxDynamicSharedMemorySize, KNN_SMEM_BYTES);

    // two no-op launches: shift ncu capture slots (3 and 6) onto the knn launches
    noop_kernel<<<1, 32>>>();
    noop_kernel<<<1, 32>>>();

    // encoder -> h0 (+ sqnorms + bf16 hi/lo)
    enc_kernel<<<NN/256, 256>>>(x, enc_w1, enc_b1, enc_w2, enc_b2);
    // EdgeConv 1
    knn7_kernel<<<NB*8, 128, KNN_SMEM_BYTES>>>();
    prep_kernel<<<NN/256, 256>>>(h0, ec1_w1, ec1_b1);
    msg_kernel<<<NN/4, 128>>>(ec1_w2, ec1_b2, h1);
    // EdgeConv 2
    knn7_kernel<<<NB*8, 128, KNN_SMEM_BYTES>>>();
    prep_kernel<<<NN/256, 256>>>(h1, ec2_w1, ec2_b1);
    msg_kernel<<<NN/4, 128>>>(ec2_w2, ec2_b2, h0);   // reuse h0 as h2
    // pool + output MLP
    pool_kernel<<<NB, 256>>>(h0, out_w1, out_b1, out_w2, out_b2, out);
}